// round 10
// baseline (speedup 1.0000x reference)
#include <cuda_runtime.h>
#include <cuda_bf16.h>

#define N      512
#define DIM    256
#define EPSV   1e-12f
#define KLOG2E 14.426950408889634f   // SCAL(=10) * log2(e)

#define NTRI   136                   // 16*17/2 triangular 32x32 tiles
#define TBLK   128                   // triplet blocks (4 anchors, 1 per warp)
#define APITCH 68                    // 272B = 17*16B
#define BPITCH 36                    // 144B = 9*16B

__device__ float    g_D[N * N];
__device__ float    g_partial[TBLK];
__device__ float    g_pcount[TBLK];
__device__ unsigned g_done = 0;

typedef unsigned long long ull;

__device__ __forceinline__ ull ffma2(ull a, ull b, ull c) {
    ull d; asm("fma.rn.f32x2 %0, %1, %2, %3;" : "=l"(d) : "l"(a), "l"(b), "l"(c));
    return d;
}
__device__ __forceinline__ ull addf2(ull a, ull b) {
    ull d; asm("add.rn.f32x2 %0, %1, %2;" : "=l"(d) : "l"(a), "l"(b));
    return d;
}
__device__ __forceinline__ void unpack2(ull v, float& lo, float& hi) {
    asm("mov.b64 {%0, %1}, %2;" : "=f"(lo), "=f"(hi) : "l"(v));
}
__device__ __forceinline__ float ex2a(float x) {
    float y; asm("ex2.approx.ftz.f32 %0, %1;" : "=f"(y) : "f"(x)); return y;
}
__device__ __forceinline__ float rcpa(float x) {
    float y; asm("rcp.approx.ftz.f32 %0, %1;" : "=f"(y) : "f"(x)); return y;
}

// ---------------------------------------------------------------------------
// Kernel 1 (unchanged from R9): lower-triangle 32x32 distance tiles,
// f32x2 packed FMA, 512 threads (4 k-quarters).
// ---------------------------------------------------------------------------
__global__ void __launch_bounds__(512)
k_dist(const float* __restrict__ feat) {
    __shared__ __align__(16) float Ad[4][16][APITCH];   // 17.4 KB
    __shared__ __align__(16) float Bt[4][16][BPITCH];   //  9.2 KB
    __shared__ float sqi[32], sqj[32];
    __shared__ ull   stg[3][128][4];                    // 12 KB

    const int tid = threadIdx.x;
    const int bid = blockIdx.x;

    int ti = (int)((sqrtf(8.f * bid + 1.f) - 1.f) * 0.5f);
    if ((ti + 1) * (ti + 2) / 2 <= bid) ++ti;
    if (ti * (ti + 1) / 2 > bid) --ti;
    const int tj = bid - ti * (ti + 1) / 2;
    const int i0 = ti * 32, j0 = tj * 32;

    const float4* f4 = reinterpret_cast<const float4*>(feat);

    {   // squared norms: 64 rows, 8 threads/row
        const int r = tid >> 3, q = tid & 7;
        const int grow = (r < 32) ? (i0 + r) : (j0 + r - 32);
        float s = 0.f;
        #pragma unroll
        for (int u = 0; u < 8; ++u) {
            const float4 v = __ldg(&f4[grow * 64 + q * 8 + u]);
            s += v.x * v.x + v.y * v.y + v.z * v.z + v.w * v.w;
        }
        s += __shfl_xor_sync(0xffffffffu, s, 1);
        s += __shfl_xor_sync(0xffffffffu, s, 2);
        s += __shfl_xor_sync(0xffffffffu, s, 4);
        if (q == 0) { if (r < 32) sqi[r] = s; else sqj[r - 32] = s; }
    }

    const int kq = tid >> 7;
    const int r7 = tid & 127;
    const int ig = r7 & 15;
    const int jg = r7 >> 4;

    ull acc00 = 0, acc01 = 0, acc10 = 0, acc11 = 0;

    const int khb = tid >> 7;
    const int rem = tid & 127;
    const int row = rem >> 2;
    const int kf  = rem & 3;

    float4 pfa = __ldg(&f4[(i0 + row) * 64 + khb * 16 + kf]);
    float4 pfb = __ldg(&f4[(j0 + row) * 64 + khb * 16 + kf]);

    for (int c = 0; c < 4; ++c) {
        __syncthreads();
        {
            const float av[4] = {pfa.x, pfa.y, pfa.z, pfa.w};
            const float bv[4] = {pfb.x, pfb.y, pfb.z, pfb.w};
            #pragma unroll
            for (int e = 0; e < 4; ++e) {
                Ad[khb][4 * kf + e][2 * row]     = av[e];
                Ad[khb][4 * kf + e][2 * row + 1] = av[e];
                Bt[khb][4 * kf + e][row]         = bv[e];
            }
        }
        __syncthreads();
        if (c < 3) {
            pfa = __ldg(&f4[(i0 + row) * 64 + khb * 16 + (c + 1) * 4 + kf]);
            pfb = __ldg(&f4[(j0 + row) * 64 + khb * 16 + (c + 1) * 4 + kf]);
        }
        const float* Ab = &Ad[kq][0][4 * ig];
        const float* Bb = &Bt[kq][0][4 * jg];
        #pragma unroll
        for (int k = 0; k < 16; ++k) {
            const ulonglong2 a = *reinterpret_cast<const ulonglong2*>(Ab + k * APITCH);
            const ulonglong2 b = *reinterpret_cast<const ulonglong2*>(Bb + k * BPITCH);
            acc00 = ffma2(a.x, b.x, acc00);
            acc01 = ffma2(a.x, b.y, acc01);
            acc10 = ffma2(a.y, b.x, acc10);
            acc11 = ffma2(a.y, b.y, acc11);
        }
    }

    __syncthreads();
    if (kq >= 1) {
        stg[kq - 1][r7][0] = acc00; stg[kq - 1][r7][1] = acc01;
        stg[kq - 1][r7][2] = acc10; stg[kq - 1][r7][3] = acc11;
    }
    __syncthreads();
    if (kq == 0) {
        #pragma unroll
        for (int s = 0; s < 3; ++s) {
            acc00 = addf2(acc00, stg[s][r7][0]);
            acc01 = addf2(acc01, stg[s][r7][1]);
            acc10 = addf2(acc10, stg[s][r7][2]);
            acc11 = addf2(acc11, stg[s][r7][3]);
        }
        float d[2][4];
        unpack2(acc00, d[0][0], d[0][1]); unpack2(acc01, d[0][2], d[0][3]);
        unpack2(acc10, d[1][0], d[1][1]); unpack2(acc11, d[1][2], d[1][3]);
        #pragma unroll
        for (int rr = 0; rr < 2; ++rr) {
            const int   orow = 2 * ig + rr;
            const float si   = sqi[orow];
            float o[4];
            #pragma unroll
            for (int cc = 0; cc < 4; ++cc)
                o[cc] = sqrtf(fmaxf(si + sqj[4 * jg + cc] - 2.f * d[rr][cc], EPSV));
            *reinterpret_cast<float4*>(&g_D[(i0 + orow) * N + j0 + 4 * jg]) =
                make_float4(o[0], o[1], o[2], o[3]);
            if (ti != tj) {
                #pragma unroll
                for (int cc = 0; cc < 4; ++cc)
                    g_D[(j0 + 4 * jg + cc) * N + i0 + orow] = o[cc];
            }
        }
    }
}

// ---------------------------------------------------------------------------
// Kernel 2: warp-autonomous triplet sums. 128 blocks x 128 threads;
// warp w owns anchor 4*bid+w. No block barriers until the 4-warp combine.
// ---------------------------------------------------------------------------
__global__ void __launch_bounds__(128)
k_triplet(const int* __restrict__ y, float* __restrict__ out) {
    __shared__ float posW[4][64];
    __shared__ float wres[4], wcnt[4];
    __shared__ float red[TBLK];
    __shared__ int   last_s;

    const int tid  = threadIdx.x;
    const int bid  = blockIdx.x;
    const int warp = tid >> 5;
    const int lane = tid & 31;
    const int a    = bid * 4 + warp;
    const float INF = __int_as_float(0x7f800000);

    const int   ya   = __ldg(&y[a]);
    const float cref = g_D[a * N + ((a + 1) & (N - 1))] * KLOG2E;

    // lane owns 16 columns: j = 128*c + 4*lane + e
    float xa[16]; int yl[16];
    #pragma unroll
    for (int c = 0; c < 4; ++c) {
        const int idx = 128 * c + 4 * lane;
        const int4   yv = *reinterpret_cast<const int4*>(y + idx);
        const float4 xv = *reinterpret_cast<const float4*>(&g_D[a * N + idx]);
        yl[4*c+0] = yv.x; yl[4*c+1] = yv.y; yl[4*c+2] = yv.z; yl[4*c+3] = yv.w;
        xa[4*c+0] = xv.x * KLOG2E; xa[4*c+1] = xv.y * KLOG2E;
        xa[4*c+2] = xv.z * KLOG2E; xa[4*c+3] = xv.w * KLOG2E;
    }

    // warp-cooperative positive scan (16 ballot rounds)
    int cnt = 0, same = 0;
    #pragma unroll
    for (int i = 0; i < 16; ++i) {
        const int  j  = 128 * (i >> 2) + 4 * lane + (i & 3);
        const bool sc = (yl[i] == ya);
        const bool v  = sc && (j != a);
        const unsigned ms = __ballot_sync(0xffffffffu, sc);
        const unsigned mv = __ballot_sync(0xffffffffu, v);
        if (v) {
            const int slot = cnt + __popc(mv & ((1u << lane) - 1u));
            posW[warp][slot] = fminf(fmaxf(ex2a(cref - xa[i]), 1e-30f), 1e30f);
        }
        cnt  += __popc(mv);
        same += __popc(ms);
    }
    __syncwarp();

    // e values for this lane's 16 negatives (INF => exact 0 contribution)
    float ex[16];
    #pragma unroll
    for (int i = 0; i < 16; ++i)
        ex[i] = (yl[i] == ya) ? INF : fmaxf(ex2a(xa[i] - cref), 1e-30f);

    // sigmoid loop: 16 independent chains per positive
    float ac0 = 0.f, ac1 = 0.f, ac2 = 0.f, ac3 = 0.f;
    for (int p = 0; p < cnt; ++p) {
        const float rp = posW[warp][p];
        #pragma unroll
        for (int i = 0; i < 16; i += 4) {
            ac0 += rcpa(fmaf(ex[i + 0], rp, 1.f));
            ac1 += rcpa(fmaf(ex[i + 1], rp, 1.f));
            ac2 += rcpa(fmaf(ex[i + 2], rp, 1.f));
            ac3 += rcpa(fmaf(ex[i + 3], rp, 1.f));
        }
    }
    float acc = (ac0 + ac1) + (ac2 + ac3);
    #pragma unroll
    for (int o = 16; o > 0; o >>= 1) acc += __shfl_xor_sync(0xffffffffu, acc, o);
    if (lane == 0) {
        wres[warp] = acc;
        wcnt[warp] = (float)(cnt * (N - same));
    }
    __syncthreads();

    if (tid == 0) {
        g_partial[bid] = (wres[0] + wres[1]) + (wres[2] + wres[3]);
        g_pcount[bid]  = (wcnt[0] + wcnt[1]) + (wcnt[2] + wcnt[3]);
        __threadfence();
        const unsigned t = atomicAdd(&g_done, 1u);
        last_s = (t == TBLK - 1);
    }
    __syncthreads();

    if (last_s) {
        __threadfence();
        red[tid] = __ldcg(&g_partial[tid]);
        __syncthreads();
        #pragma unroll
        for (int st = 64; st > 0; st >>= 1) {
            if (tid < st) red[tid] += red[tid + st];
            __syncthreads();
        }
        const float tot = red[0];
        __syncthreads();
        red[tid] = __ldcg(&g_pcount[tid]);
        __syncthreads();
        #pragma unroll
        for (int st = 64; st > 0; st >>= 1) {
            if (tid < st) red[tid] += red[tid + st];
            __syncthreads();
        }
        if (tid == 0) {
            out[0] = tot / red[0];
            g_done = 0;                   // reset for next graph replay
        }
    }
}

// ---------------------------------------------------------------------------
extern "C" void kernel_launch(void* const* d_in, const int* in_sizes, int n_in,
                              void* d_out, int out_size) {
    const float* feat = (const float*)d_in[0];
    // d_in[1] = logits (unused by the loss)
    const int*   y    = (const int*)d_in[2];
    float*       out  = (float*)d_out;

    k_dist   <<<NTRI, 512>>>(feat);
    k_triplet<<<TBLK, 128>>>(y, out);
}